// round 16
// baseline (speedup 1.0000x reference)
#include <cuda_runtime.h>
#include <math.h>

// Problem shape (fixed by setup_inputs)
#define BATCH 256
#define TLEN  1024
#define DDIM  256
#define LOG2PI 1.8378770664093453f

// Main-kernel tiling (proven-best main: 48.2-49.0us across 6 replays)
#define GBTOT   8                 // batches per block (2 halves x 4)
#define GBH     4                 // batches per thread half
#define NCHUNK  32                // t-chunks
#define CHUNK   (TLEN / NCHUNK)   // 32
#define BSTRIDE (TLEN * DDIM)     // elements between batches (1MB)

// Table: 2 SoA sections (A, R); C = -mu(1-A)R is recomputed in-loop (it is
// per-d, amortized over 4 batches -> ~0.5 extra FMA/element).
#define SEC    ((TLEN - 1) * DDIM)
#define SEC_A  0
#define SEC_R  SEC
__device__ float g_tabf[2 * SEC];   // A=exp(-k dt), R=1/sqrt(q)
__device__ float g_r0[DDIM];        // 1/sqrt(var0)
__device__ float g_c0[DDIM];        // -mu/sqrt(var0)
__device__ float g_row[TLEN];       // per-t row sums of log q + LOG2PI

__device__ __forceinline__ float softplusf(float x) {
    return (x > 20.f) ? x : log1pf(expf(x));
}

// ---------------------------------------------------------------------------
// Kernel 1: precompute table + per-row log constants; zero the output.
// grid = TLEN blocks, block = 128 threads; each thread owns 2 consecutive d's.
// ---------------------------------------------------------------------------
__global__ __launch_bounds__(128)
void k_precompute(const float* __restrict__ ts,
                  const float* __restrict__ log_kappa,
                  const float* __restrict__ log_sigma,
                  const float* __restrict__ mu,
                  float* __restrict__ out, int out_size) {
    const int t  = blockIdx.x;
    const int p  = threadIdx.x;        // d-pair: d = {2p, 2p+1}
    const int d0 = 2 * p;

    const float2 lk2 = *(const float2*)(log_kappa + d0);
    const float2 ls2 = *(const float2*)(log_sigma + d0);
    const float kx = softplusf(lk2.x) + 1e-6f;
    const float ky = softplusf(lk2.y) + 1e-6f;
    const float sx = softplusf(ls2.x) + 1e-6f;
    const float sy = softplusf(ls2.y) + 1e-6f;
    const float s2x = sx * sx, s2y = sy * sy;

    float elem;
    if (t == 0) {
        const float2 mu2 = *(const float2*)(mu + d0);
        float v0x = fmaxf(s2x / (2.0f * kx), 1e-10f);
        float v0y = fmaxf(s2y / (2.0f * ky), 1e-10f);
        float r0x = rsqrtf(v0x), r0y = rsqrtf(v0y);
        *(float2*)(g_r0 + d0) = make_float2(r0x, r0y);
        *(float2*)(g_c0 + d0) = make_float2(-mu2.x * r0x, -mu2.y * r0y);
        elem = logf(v0x) + logf(v0y) + 2.0f * LOG2PI;
        for (int i = p; i < out_size; i += blockDim.x) out[i] = 0.0f;
    } else {
        float2 tc = *(const float2*)(ts + t * DDIM + d0);
        float2 tp = *(const float2*)(ts + (t - 1) * DDIM + d0);
        float dtx = fmaxf(tc.x - tp.x, 1e-6f);
        float dty = fmaxf(tc.y - tp.y, 1e-6f);
        float Ax = expf(-kx * dtx);
        float Ay = expf(-ky * dty);
        float qx = fmaxf(s2x * (-expm1f(-2.0f * kx * dtx)) / (2.0f * kx), 1e-10f);
        float qy = fmaxf(s2y * (-expm1f(-2.0f * ky * dty)) / (2.0f * ky), 1e-10f);
        float Rx = rsqrtf(qx), Ry = rsqrtf(qy);
        const int idx = (t - 1) * DDIM + d0;
        *(float2*)(g_tabf + SEC_A + idx) = make_float2(Ax, Ay);
        *(float2*)(g_tabf + SEC_R + idx) = make_float2(Rx, Ry);
        elem = logf(qx) + logf(qy) + 2.0f * LOG2PI;
    }

    // block reduce elem (128 -> 1)
    const int lane = p & 31;
    const int warp = p >> 5;
    __shared__ float sm[4];
#pragma unroll
    for (int o = 16; o > 0; o >>= 1) elem += __shfl_down_sync(0xffffffffu, elem, o);
    if (lane == 0) sm[warp] = elem;
    __syncthreads();
    if (p == 0) g_row[t] = sm[0] + sm[1] + sm[2] + sm[3];
}

// ---------------------------------------------------------------------------
// Kernel 2: main streaming pass. grid = 1024 blocks, block = 256 threads.
// dv = tid&127 covers d = {2dv, 2dv+1}; h = tid>>7 handles 4 batches.
// 4-deep t-window: all 16 y LDG.64 front-batched; table (A,R) loads JIT;
// C = (A-1)*R*mu recomputed per step (shared across 4 batches).
// z = fma(fma(-A,prev,y), R, C); acc = fma(z,z,acc).
// ---------------------------------------------------------------------------
__global__ __launch_bounds__(256, 4)
void k_main(const float* __restrict__ y, const float* __restrict__ mu,
            float* __restrict__ out) {
    const int c     = blockIdx.x & (NCHUNK - 1);
    const int bbase = (blockIdx.x >> 5) * GBTOT;
    const int tid   = threadIdx.x;
    const int dv    = tid & 127;
    const int h     = tid >> 7;

    const float2 mu2 = *(const float2*)(mu + 2 * dv);
    const float* __restrict__ yb =
        y + (size_t)(bbase + h * GBH) * BSTRIDE + 2 * dv;

    const int tstart = c * CHUNK;
    const int t0   = (c == 0) ? 1 : tstart;
    const int tend = tstart + CHUNK;

    float2 prev[GBH];
    float  acc[GBH];
#pragma unroll
    for (int g = 0; g < GBH; g++)
        prev[g] = *(const float2*)(yb + (size_t)(t0 - 1) * DDIM + g * BSTRIDE);

    if (c == 0) {
        float2 r0 = *(const float2*)(g_r0 + 2 * dv);
        float2 c0 = *(const float2*)(g_c0 + 2 * dv);
#pragma unroll
        for (int g = 0; g < GBH; g++) {
            float zx = fmaf(prev[g].x, r0.x, c0.x);
            float zy = fmaf(prev[g].y, r0.y, c0.y);
            acc[g] = zx * zx + zy * zy;
        }
    } else {
#pragma unroll
        for (int g = 0; g < GBH; g++) acc[g] = 0.0f;
    }

    const float* __restrict__ tb = g_tabf + 2 * dv;

    int t = t0;
    for (; t + 3 < tend; t += 4) {
        // ---- front-batched y loads: 16 LDG.64 back-to-back (DRAM MLP) ----
        float2 yv[4][GBH];
        const float* yt = yb + (size_t)t * DDIM;
#pragma unroll
        for (int u = 0; u < 4; u++)
#pragma unroll
            for (int g = 0; g < GBH; g++)
                yv[u][g] = __ldcs((const float2*)(yt + u * DDIM + g * BSTRIDE));

        // ---- per-step table loads (L1/L2 hits) + compute ----
        const float* tt = tb + (size_t)(t - 1) * DDIM;
#pragma unroll
        for (int u = 0; u < 4; u++) {
            float2 A = __ldg((const float2*)(tt + u * DDIM + SEC_A));
            float2 R = __ldg((const float2*)(tt + u * DDIM + SEC_R));
            float Ccx = (A.x - 1.0f) * R.x * mu2.x;   // = -mu(1-A)R
            float Ccy = (A.y - 1.0f) * R.y * mu2.y;
#pragma unroll
            for (int g = 0; g < GBH; g++) {
                float xx = fmaf(-A.x, prev[g].x, yv[u][g].x);
                float xy = fmaf(-A.y, prev[g].y, yv[u][g].y);
                float zx = fmaf(xx, R.x, Ccx);
                float zy = fmaf(xy, R.y, Ccy);
                acc[g] = fmaf(zx, zx, acc[g]);
                acc[g] = fmaf(zy, zy, acc[g]);
                prev[g] = yv[u][g];
            }
        }
    }
    // remainder (only for c==0: 3 iterations)
    for (; t < tend; ++t) {
        const float* tt = tb + (size_t)(t - 1) * DDIM;
        float2 A = __ldg((const float2*)(tt + SEC_A));
        float2 R = __ldg((const float2*)(tt + SEC_R));
        float Ccx = (A.x - 1.0f) * R.x * mu2.x;
        float Ccy = (A.y - 1.0f) * R.y * mu2.y;
#pragma unroll
        for (int g = 0; g < GBH; g++) {
            float2 yv = __ldcs((const float2*)(yb + (size_t)t * DDIM + g * BSTRIDE));
            float xx = fmaf(-A.x, prev[g].x, yv.x);
            float xy = fmaf(-A.y, prev[g].y, yv.y);
            float zx = fmaf(xx, R.x, Ccx);
            float zy = fmaf(xy, R.y, Ccy);
            acc[g] = fmaf(zx, zx, acc[g]);
            acc[g] = fmaf(zy, zy, acc[g]);
            prev[g] = yv;
        }
    }

    // ---- reduce: warp shuffle per g, cross-warp via smem ----
    const int lane = tid & 31;
    const int warp = tid >> 5;
    __shared__ float sm[8][GBH];
#pragma unroll
    for (int g = 0; g < GBH; g++) {
        float v = acc[g];
#pragma unroll
        for (int o = 16; o > 0; o >>= 1) v += __shfl_down_sync(0xffffffffu, v, o);
        if (lane == 0) sm[warp][g] = v;
    }
    __syncthreads();

    // chunk constant: sum of this chunk's 32 g_row entries (warp 0)
    float chunkC = 0.0f;
    if (warp == 0) {
        float v = g_row[tstart + lane];
#pragma unroll
        for (int o = 16; o > 0; o >>= 1) v += __shfl_down_sync(0xffffffffu, v, o);
        chunkC = __shfl_sync(0xffffffffu, v, 0);
    }

    if (tid < GBTOT) {
        int h2 = tid >> 2;
        int g  = tid & 3;
        float s = sm[h2 * 4 + 0][g] + sm[h2 * 4 + 1][g]
                + sm[h2 * 4 + 2][g] + sm[h2 * 4 + 3][g];
        atomicAdd(&out[bbase + h2 * GBH + g], -0.5f * (s + chunkC));
    }
}

extern "C" void kernel_launch(void* const* d_in, const int* in_sizes, int n_in,
                              void* d_out, int out_size) {
    const float* y  = (const float*)d_in[0];
    const float* ts = (const float*)d_in[1];
    const float* mu = (const float*)d_in[2];
    const float* lk = (const float*)d_in[3];
    const float* ls = (const float*)d_in[4];
    float* out = (float*)d_out;

    k_precompute<<<TLEN, 128>>>(ts, lk, ls, mu, out, out_size);
    k_main<<<(BATCH / GBTOT) * NCHUNK, 256>>>(y, mu, out);
}

// round 17
// speedup vs baseline: 1.0050x; 1.0050x over previous
#include <cuda_runtime.h>
#include <math.h>

// Problem shape (fixed by setup_inputs)
#define BATCH 256
#define TLEN  1024
#define DDIM  256
#define LOG2PI 1.8378770664093453f

// Main-kernel tiling (proven-best main: 48.06us in R16)
#define GBTOT   8                 // batches per block (2 halves x 4)
#define GBH     4                 // batches per thread half
#define NCHUNK  32                // t-chunks
#define CHUNK   (TLEN / NCHUNK)   // 32
#define BSTRIDE (TLEN * DDIM)     // elements between batches (1MB)

// Table: 2 SoA sections (A, R); C = -mu(1-A)R recomputed in-loop.
#define SEC    ((TLEN - 1) * DDIM)
#define SEC_A  0
#define SEC_R  SEC
__device__ float g_tabf[2 * SEC];   // A=exp(-k dt), R=1/sqrt(q)
__device__ float g_r0[DDIM];        // 1/sqrt(var0)
__device__ float g_c0[DDIM];        // -mu/sqrt(var0)
__device__ float g_row[TLEN];       // per-t row sums of log q + LOG2PI

__device__ __forceinline__ float softplusf(float x) {
    return (x > 20.f) ? x : log1pf(expf(x));
}

// ---------------------------------------------------------------------------
// Kernel 1: precompute table + per-row log constants; zero the output.
// Triggers programmatic launch completion at entry so k_main's prologue
// (launch ramp + table-independent y loads) overlaps this kernel.
// ---------------------------------------------------------------------------
__global__ __launch_bounds__(128)
void k_precompute(const float* __restrict__ ts,
                  const float* __restrict__ log_kappa,
                  const float* __restrict__ log_sigma,
                  const float* __restrict__ mu,
                  float* __restrict__ out, int out_size) {
    cudaTriggerProgrammaticLaunchCompletion();

    const int t  = blockIdx.x;
    const int p  = threadIdx.x;        // d-pair: d = {2p, 2p+1}
    const int d0 = 2 * p;

    const float2 lk2 = *(const float2*)(log_kappa + d0);
    const float2 ls2 = *(const float2*)(log_sigma + d0);
    const float kx = softplusf(lk2.x) + 1e-6f;
    const float ky = softplusf(lk2.y) + 1e-6f;
    const float sx = softplusf(ls2.x) + 1e-6f;
    const float sy = softplusf(ls2.y) + 1e-6f;
    const float s2x = sx * sx, s2y = sy * sy;

    float elem;
    if (t == 0) {
        const float2 mu2 = *(const float2*)(mu + d0);
        float v0x = fmaxf(s2x / (2.0f * kx), 1e-10f);
        float v0y = fmaxf(s2y / (2.0f * ky), 1e-10f);
        float r0x = rsqrtf(v0x), r0y = rsqrtf(v0y);
        *(float2*)(g_r0 + d0) = make_float2(r0x, r0y);
        *(float2*)(g_c0 + d0) = make_float2(-mu2.x * r0x, -mu2.y * r0y);
        elem = logf(v0x) + logf(v0y) + 2.0f * LOG2PI;
        for (int i = p; i < out_size; i += blockDim.x) out[i] = 0.0f;
    } else {
        float2 tc = *(const float2*)(ts + t * DDIM + d0);
        float2 tp = *(const float2*)(ts + (t - 1) * DDIM + d0);
        float dtx = fmaxf(tc.x - tp.x, 1e-6f);
        float dty = fmaxf(tc.y - tp.y, 1e-6f);
        float Ax = expf(-kx * dtx);
        float Ay = expf(-ky * dty);
        float qx = fmaxf(s2x * (-expm1f(-2.0f * kx * dtx)) / (2.0f * kx), 1e-10f);
        float qy = fmaxf(s2y * (-expm1f(-2.0f * ky * dty)) / (2.0f * ky), 1e-10f);
        float Rx = rsqrtf(qx), Ry = rsqrtf(qy);
        const int idx = (t - 1) * DDIM + d0;
        *(float2*)(g_tabf + SEC_A + idx) = make_float2(Ax, Ay);
        *(float2*)(g_tabf + SEC_R + idx) = make_float2(Rx, Ry);
        elem = logf(qx) + logf(qy) + 2.0f * LOG2PI;
    }

    const int lane = p & 31;
    const int warp = p >> 5;
    __shared__ float sm[4];
#pragma unroll
    for (int o = 16; o > 0; o >>= 1) elem += __shfl_down_sync(0xffffffffu, elem, o);
    if (lane == 0) sm[warp] = elem;
    __syncthreads();
    if (p == 0) g_row[t] = sm[0] + sm[1] + sm[2] + sm[3];
}

// ---------------------------------------------------------------------------
// Kernel 2: main streaming pass (R16 best-main configuration + PDL).
// Issues table-independent prev-row y loads BEFORE gridDependencySynchronize
// so they overlap k_precompute's tail; all table/g_r0 reads come after.
// ---------------------------------------------------------------------------
__global__ __launch_bounds__(256, 4)
void k_main(const float* __restrict__ y, const float* __restrict__ mu,
            float* __restrict__ out) {
    const int c     = blockIdx.x & (NCHUNK - 1);
    const int bbase = (blockIdx.x >> 5) * GBTOT;
    const int tid   = threadIdx.x;
    const int dv    = tid & 127;
    const int h     = tid >> 7;

    const float2 mu2 = *(const float2*)(mu + 2 * dv);
    const float* __restrict__ yb =
        y + (size_t)(bbase + h * GBH) * BSTRIDE + 2 * dv;

    const int tstart = c * CHUNK;
    const int t0   = (c == 0) ? 1 : tstart;
    const int tend = tstart + CHUNK;

    // ---- table-independent DRAM work first (overlaps precompute) ----
    float2 prev[GBH];
#pragma unroll
    for (int g = 0; g < GBH; g++)
        prev[g] = __ldcs((const float2*)(yb + (size_t)(t0 - 1) * DDIM + g * BSTRIDE));

    // ---- wait for k_precompute's table writes to be visible ----
    cudaGridDependencySynchronize();

    float acc[GBH];
    if (c == 0) {
        float2 r0 = *(const float2*)(g_r0 + 2 * dv);
        float2 c0 = *(const float2*)(g_c0 + 2 * dv);
#pragma unroll
        for (int g = 0; g < GBH; g++) {
            float zx = fmaf(prev[g].x, r0.x, c0.x);
            float zy = fmaf(prev[g].y, r0.y, c0.y);
            acc[g] = zx * zx + zy * zy;
        }
    } else {
#pragma unroll
        for (int g = 0; g < GBH; g++) acc[g] = 0.0f;
    }

    const float* __restrict__ tb = g_tabf + 2 * dv;

    int t = t0;
    for (; t + 3 < tend; t += 4) {
        // ---- front-batched y loads: 16 LDG.64 back-to-back (DRAM MLP) ----
        float2 yv[4][GBH];
        const float* yt = yb + (size_t)t * DDIM;
#pragma unroll
        for (int u = 0; u < 4; u++)
#pragma unroll
            for (int g = 0; g < GBH; g++)
                yv[u][g] = __ldcs((const float2*)(yt + u * DDIM + g * BSTRIDE));

        // ---- per-step table loads (L1/L2 hits) + compute ----
        const float* tt = tb + (size_t)(t - 1) * DDIM;
#pragma unroll
        for (int u = 0; u < 4; u++) {
            float2 A = __ldg((const float2*)(tt + u * DDIM + SEC_A));
            float2 R = __ldg((const float2*)(tt + u * DDIM + SEC_R));
            float Ccx = (A.x - 1.0f) * R.x * mu2.x;   // = -mu(1-A)R
            float Ccy = (A.y - 1.0f) * R.y * mu2.y;
#pragma unroll
            for (int g = 0; g < GBH; g++) {
                float xx = fmaf(-A.x, prev[g].x, yv[u][g].x);
                float xy = fmaf(-A.y, prev[g].y, yv[u][g].y);
                float zx = fmaf(xx, R.x, Ccx);
                float zy = fmaf(xy, R.y, Ccy);
                acc[g] = fmaf(zx, zx, acc[g]);
                acc[g] = fmaf(zy, zy, acc[g]);
                prev[g] = yv[u][g];
            }
        }
    }
    // remainder (only for c==0: 3 iterations)
    for (; t < tend; ++t) {
        const float* tt = tb + (size_t)(t - 1) * DDIM;
        float2 A = __ldg((const float2*)(tt + SEC_A));
        float2 R = __ldg((const float2*)(tt + SEC_R));
        float Ccx = (A.x - 1.0f) * R.x * mu2.x;
        float Ccy = (A.y - 1.0f) * R.y * mu2.y;
#pragma unroll
        for (int g = 0; g < GBH; g++) {
            float2 yv = __ldcs((const float2*)(yb + (size_t)t * DDIM + g * BSTRIDE));
            float xx = fmaf(-A.x, prev[g].x, yv.x);
            float xy = fmaf(-A.y, prev[g].y, yv.y);
            float zx = fmaf(xx, R.x, Ccx);
            float zy = fmaf(xy, R.y, Ccy);
            acc[g] = fmaf(zx, zx, acc[g]);
            acc[g] = fmaf(zy, zy, acc[g]);
            prev[g] = yv;
        }
    }

    // ---- reduce: warp shuffle per g, cross-warp via smem ----
    const int lane = tid & 31;
    const int warp = tid >> 5;
    __shared__ float sm[8][GBH];
#pragma unroll
    for (int g = 0; g < GBH; g++) {
        float v = acc[g];
#pragma unroll
        for (int o = 16; o > 0; o >>= 1) v += __shfl_down_sync(0xffffffffu, v, o);
        if (lane == 0) sm[warp][g] = v;
    }
    __syncthreads();

    // chunk constant: sum of this chunk's 32 g_row entries (warp 0)
    float chunkC = 0.0f;
    if (warp == 0) {
        float v = g_row[tstart + lane];
#pragma unroll
        for (int o = 16; o > 0; o >>= 1) v += __shfl_down_sync(0xffffffffu, v, o);
        chunkC = __shfl_sync(0xffffffffu, v, 0);
    }

    if (tid < GBTOT) {
        int h2 = tid >> 2;
        int g  = tid & 3;
        float s = sm[h2 * 4 + 0][g] + sm[h2 * 4 + 1][g]
                + sm[h2 * 4 + 2][g] + sm[h2 * 4 + 3][g];
        atomicAdd(&out[bbase + h2 * GBH + g], -0.5f * (s + chunkC));
    }
}

extern "C" void kernel_launch(void* const* d_in, const int* in_sizes, int n_in,
                              void* d_out, int out_size) {
    const float* y  = (const float*)d_in[0];
    const float* ts = (const float*)d_in[1];
    const float* mu = (const float*)d_in[2];
    const float* lk = (const float*)d_in[3];
    const float* ls = (const float*)d_in[4];
    float* out = (float*)d_out;

    k_precompute<<<TLEN, 128>>>(ts, lk, ls, mu, out, out_size);

    // Launch k_main with Programmatic Dependent Launch: it starts while
    // k_precompute is still running; cudaGridDependencySynchronize() inside
    // k_main orders all table reads after k_precompute completion.
    cudaLaunchAttribute attrs[1];
    attrs[0].id = cudaLaunchAttributeProgrammaticStreamSerialization;
    attrs[0].val.programmaticStreamSerializationAllowed = 1;

    cudaLaunchConfig_t cfg = {};
    cfg.gridDim  = dim3((BATCH / GBTOT) * NCHUNK, 1, 1);
    cfg.blockDim = dim3(256, 1, 1);
    cfg.dynamicSmemBytes = 0;
    cfg.stream = 0;
    cfg.attrs = attrs;
    cfg.numAttrs = 1;

    cudaLaunchKernelEx(&cfg, k_main, y, mu, out);
}